// round 13
// baseline (speedup 1.0000x reference)
#include <cuda_runtime.h>
#include <cuda_fp16.h>

#define Nn   100000
#define Ee   1600000
#define ETOT 1700000
#define Gg   1024
#define EMB  32
#define DC   128
#define Dd   64
#define LNEPS 1e-5f
#define NEG_GAT 0.2f
#define NEG_ACT 0.05f
#define NB_SCAN 98   // ceil(Nn/1024)

// ---------------- scratch ----------------
__device__ __half g_xwh[Nn * DC];       // 25.6 MB fp16 transformed feats (gather payload)
__device__ float g_h1[Nn * DC];         // 51.2 MB layer-1 output (fp32 for gemm2 accuracy)
__device__ float g_als[Nn * 2];
__device__ float g_ald[Nn * 2];
__device__ int   g_esrc[ETOT];
__device__ int   g_deg[Nn];
__device__ int   g_rowptr[Nn + 1];
__device__ int   g_cursor[Nn];
__device__ int   g_bsum[128];
__device__ int   g_bpre[128];
__device__ float g_ge[Nn];
__device__ float g_gsum[Gg];

__device__ __forceinline__ float lrelu(float x, float a) { return x >= 0.f ? x : a * x; }

// packed f32x2 helpers (Blackwell FFMA2)
__device__ __forceinline__ unsigned long long pk2(float b) {
    unsigned long long r;
    asm("mov.b64 %0, {%1, %1};" : "=l"(r) : "f"(b));
    return r;
}
__device__ __forceinline__ void pfma(unsigned long long& d, unsigned long long a, unsigned long long b) {
    asm("fma.rn.f32x2 %0, %1, %2, %0;" : "+l"(d) : "l"(a), "l"(b));
}
__device__ __forceinline__ float2 upk(unsigned long long v) {
    float2 f;
    asm("mov.b64 {%0, %1}, %2;" : "=f"(f.x), "=f"(f.y) : "l"(v));
    return f;
}
__device__ __forceinline__ void lds_v2u64(unsigned long long& lo, unsigned long long& hi, unsigned saddr) {
    asm volatile("ld.shared.v2.u64 {%0, %1}, [%2];" : "=l"(lo), "=l"(hi) : "r"(saddr));
}
__device__ __forceinline__ void lds_u64(unsigned long long& v, unsigned saddr) {
    asm volatile("ld.shared.u64 %0, [%1];" : "=l"(v) : "r"(saddr));
}

// store float4 as 4 halfs (8B) at row n, lane slot
__device__ __forceinline__ void st_h4(int n, int lane, float a, float b, float c, float d) {
    __half2 h01 = __floats2half2_rn(a, b);
    __half2 h23 = __floats2half2_rn(c, d);
    uint2 uv;
    uv.x = *reinterpret_cast<unsigned*>(&h01);
    uv.y = *reinterpret_cast<unsigned*>(&h23);
    ((uint2*)(g_xwh + (size_t)n * DC))[lane] = uv;
}

// ---------------- init ----------------
__global__ void k_zero(float* zout) {
    int i = blockIdx.x * blockDim.x + threadIdx.x;
    if (i < Nn) g_deg[i] = 1;   // self-loop contributes exactly 1 per node
    if (i < Gg) g_gsum[i] = 0.f;
    if (i < Gg * DC) zout[i] = 0.f;
}

// ---------------- CSR build ----------------
// count only real edges (self-loops pre-counted in k_zero), int4 loads
__global__ void k_count(const int* __restrict__ ei) {
    int i = blockIdx.x * blockDim.x + threadIdx.x;   // i indexes groups of 4
    if (i >= Ee / 4) return;
    int4 d4 = ((const int4*)(ei + Ee))[i];
    atomicAdd(&g_deg[d4.x], 1);
    atomicAdd(&g_deg[d4.y], 1);
    atomicAdd(&g_deg[d4.z], 1);
    atomicAdd(&g_deg[d4.w], 1);
}

__global__ void k_scan_local() {
    __shared__ int wsum[8];
    int t = threadIdx.x, lane = t & 31, warp = t >> 5;
    int base = blockIdx.x * 1024 + t * 4;
    int v0 = (base + 0 < Nn) ? g_deg[base + 0] : 0;
    int v1 = (base + 1 < Nn) ? g_deg[base + 1] : 0;
    int v2 = (base + 2 < Nn) ? g_deg[base + 2] : 0;
    int v3 = (base + 3 < Nn) ? g_deg[base + 3] : 0;
    int s = v0 + v1 + v2 + v3;
    int inc = s;
    #pragma unroll
    for (int o = 1; o < 32; o <<= 1) {
        int x = __shfl_up_sync(~0u, inc, o);
        if (lane >= o) inc += x;
    }
    if (lane == 31) wsum[warp] = inc;
    __syncthreads();
    if (t < 8) {
        int ws = wsum[t];
        #pragma unroll
        for (int o = 1; o < 8; o <<= 1) {
            int x = __shfl_up_sync(0xffu, ws, o);
            if (t >= o) ws += x;
        }
        wsum[t] = ws;
        if (t == 7) g_bsum[blockIdx.x] = ws;
    }
    __syncthreads();
    int warpoff = warp ? wsum[warp - 1] : 0;
    int e0 = warpoff + inc - s;
    int e1 = e0 + v0, e2 = e1 + v1, e3 = e2 + v2;
    if (base + 0 < Nn) g_rowptr[base + 0] = e0;
    if (base + 1 < Nn) g_rowptr[base + 1] = e1;
    if (base + 2 < Nn) g_rowptr[base + 2] = e2;
    if (base + 3 < Nn) g_rowptr[base + 3] = e3;
}

__global__ void k_scan_mid() {
    int lane = threadIdx.x;
    int base = lane * 4;
    int v0 = (base + 0 < NB_SCAN) ? g_bsum[base + 0] : 0;
    int v1 = (base + 1 < NB_SCAN) ? g_bsum[base + 1] : 0;
    int v2 = (base + 2 < NB_SCAN) ? g_bsum[base + 2] : 0;
    int v3 = (base + 3 < NB_SCAN) ? g_bsum[base + 3] : 0;
    int s = v0 + v1 + v2 + v3;
    int inc = s;
    #pragma unroll
    for (int o = 1; o < 32; o <<= 1) {
        int x = __shfl_up_sync(~0u, inc, o);
        if (lane >= o) inc += x;
    }
    int e0 = inc - s;
    int e1 = e0 + v0, e2 = e1 + v1, e3 = e2 + v2;
    if (base + 0 < 128) g_bpre[base + 0] = e0;
    if (base + 1 < 128) g_bpre[base + 1] = e1;
    if (base + 2 < 128) g_bpre[base + 2] = e2;
    if (base + 3 < 128) g_bpre[base + 3] = e3;
    if (lane == 31) g_rowptr[Nn] = inc;
}

__global__ void k_scan_add() {
    int i = blockIdx.x * blockDim.x + threadIdx.x;
    if (i >= Nn) return;
    int r = g_rowptr[i] + g_bpre[i >> 10];
    g_rowptr[i] = r;
    g_cursor[i] = r;
}

// vectorized scatter: 4 real edges/thread; tail threads place self-loops
__global__ void k_scatter(const int* __restrict__ ei) {
    int i = blockIdx.x * blockDim.x + threadIdx.x;
    if (i < Ee / 4) {
        int4 s4 = ((const int4*)ei)[i];
        int4 d4 = ((const int4*)(ei + Ee))[i];
        g_esrc[atomicAdd(&g_cursor[d4.x], 1)] = s4.x;
        g_esrc[atomicAdd(&g_cursor[d4.y], 1)] = s4.y;
        g_esrc[atomicAdd(&g_cursor[d4.z], 1)] = s4.z;
        g_esrc[atomicAdd(&g_cursor[d4.w], 1)] = s4.w;
    } else {
        int n = i - Ee / 4;
        if (n < Nn) g_esrc[atomicAdd(&g_cursor[n], 1)] = n;
    }
}

// ---------------- fused embed + LN + GEMM 32->128, 4 nodes/warp, pfma ----------------
__global__ void __launch_bounds__(256) k_embgemm1(
        const int* __restrict__ x, const float* __restrict__ emb,
        const float* __restrict__ lng, const float* __restrict__ lnb,
        const float* __restrict__ W1, const float* __restrict__ asrc,
        const float* __restrict__ adst) {
    __shared__ float Ws[EMB * DC];  // 16 KB
    int t = threadIdx.x, lane = t & 31, warp = t >> 5;
    for (int i = t; i < EMB * DC; i += 256) Ws[i] = W1[i];
    __syncthreads();
    unsigned sb = (unsigned)__cvta_generic_to_shared(Ws);
    int n0 = blockIdx.x * 32 + warp * 4;
    float lg = lng[lane], lb = lnb[lane];
    float xv[4];
    #pragma unroll
    for (int q = 0; q < 4; q++) {
        int n = n0 + q;
        int v = (n < Nn) ? x[n] : 0;
        float val = emb[v * EMB + lane];
        float s = val;
        #pragma unroll
        for (int o = 16; o; o >>= 1) s += __shfl_xor_sync(~0u, s, o);
        float mu = s * (1.f / EMB);
        float d = val - mu;
        float qq = d * d;
        #pragma unroll
        for (int o = 16; o; o >>= 1) qq += __shfl_xor_sync(~0u, qq, o);
        xv[q] = d * rsqrtf(qq * (1.f / EMB) + LNEPS) * lg + lb;
    }
    unsigned long long ac[4][2];
    #pragma unroll
    for (int q = 0; q < 4; q++) { ac[q][0] = 0; ac[q][1] = 0; }
    #pragma unroll
    for (int k = 0; k < 32; k++) {
        unsigned long long wlo, whi;
        lds_v2u64(wlo, whi, sb + ((k * 32 + lane) << 4));
        #pragma unroll
        for (int q = 0; q < 4; q++) {
            float b = __shfl_sync(~0u, xv[q], k);
            unsigned long long p = pk2(b);
            pfma(ac[q][0], p, wlo);
            pfma(ac[q][1], p, whi);
        }
    }
    float4 as = __ldg((const float4*)asrc + lane);
    float4 ad = __ldg((const float4*)adst + lane);
    #pragma unroll
    for (int q = 0; q < 4; q++) {
        int n = n0 + q;
        float2 lo = upk(ac[q][0]), hi = upk(ac[q][1]);
        float ps = lo.x * as.x + lo.y * as.y + hi.x * as.z + hi.y * as.w;
        float pd = lo.x * ad.x + lo.y * ad.y + hi.x * ad.z + hi.y * ad.w;
        #pragma unroll
        for (int o = 8; o; o >>= 1) {
            ps += __shfl_xor_sync(~0u, ps, o);
            pd += __shfl_xor_sync(~0u, pd, o);
        }
        if (n < Nn) {
            st_h4(n, lane, lo.x, lo.y, hi.x, hi.y);
            if ((lane & 15) == 0) {
                int h = lane >> 4;
                g_als[n * 2 + h] = ps;
                g_ald[n * 2 + h] = pd;
            }
        }
    }
}

// ---------------- GEMM 128->128, 8 nodes/warp, packed f32x2 ----------------
__global__ void __launch_bounds__(256) k_gemm2(const float* __restrict__ W2,
                                               const float* __restrict__ asrc,
                                               const float* __restrict__ adst) {
    __shared__ float Ws[64 * DC];  // 32 KB
    int t = threadIdx.x, lane = t & 31, warp = t >> 5;
    unsigned sb = (unsigned)__cvta_generic_to_shared(Ws);
    int n0 = blockIdx.x * 64 + warp * 8;
    float xv[8][4];
    unsigned long long ac[8][2];
    #pragma unroll
    for (int q = 0; q < 8; q++) {
        int nq = n0 + q; if (nq > Nn - 1) nq = Nn - 1;
        float4 r = ((const float4*)(g_h1 + (size_t)nq * DC))[lane];
        xv[q][0] = r.x; xv[q][1] = r.y; xv[q][2] = r.z; xv[q][3] = r.w;
        ac[q][0] = 0; ac[q][1] = 0;
    }
    for (int ph = 0; ph < 2; ++ph) {
        __syncthreads();
        for (int i = t; i < 64 * DC; i += 256) Ws[i] = W2[ph * 64 * DC + i];
        __syncthreads();
        #pragma unroll
        for (int k4 = 0; k4 < 16; k4++) {
            int ksel = ph * 16 + k4;
            #pragma unroll
            for (int c = 0; c < 4; c++) {
                unsigned long long wlo, whi;
                lds_v2u64(wlo, whi, sb + (((4 * k4 + c) * 32 + lane) << 4));
                #pragma unroll
                for (int q = 0; q < 8; q++) {
                    float b = __shfl_sync(~0u, xv[q][c], ksel);
                    unsigned long long p = pk2(b);
                    pfma(ac[q][0], p, wlo);
                    pfma(ac[q][1], p, whi);
                }
            }
        }
    }
    float4 as = __ldg((const float4*)asrc + lane);
    float4 ad = __ldg((const float4*)adst + lane);
    #pragma unroll
    for (int q = 0; q < 8; q++) {
        int n = n0 + q;
        float2 lo = upk(ac[q][0]), hi = upk(ac[q][1]);
        float ps = lo.x * as.x + lo.y * as.y + hi.x * as.z + hi.y * as.w;
        float pd = lo.x * ad.x + lo.y * ad.y + hi.x * ad.z + hi.y * ad.w;
        #pragma unroll
        for (int o = 8; o; o >>= 1) {
            ps += __shfl_xor_sync(~0u, ps, o);
            pd += __shfl_xor_sync(~0u, pd, o);
        }
        if (n < Nn) {
            st_h4(n, lane, lo.x, lo.y, hi.x, hi.y);
            if ((lane & 15) == 0) {
                int h = lane >> 4;
                g_als[n * 2 + h] = ps;
                g_ald[n * 2 + h] = pd;
            }
        }
    }
}

// ---------------- GAT aggregation: depth-4 pipeline, fp16 gather ----------------
#define AGG_LOAD(SLOT, IDX)                                                  \
    if ((IDX) < end) {                                                       \
        int s = g_esrc[(IDX)];                                               \
        a##SLOT = *(const float2*)(g_als + 2 * s);                           \
        u##SLOT = ((const uint2*)(g_xwh + (size_t)s * DC))[lane];            \
    }

#define AGG_CONSUME(SLOT)                                                    \
    {                                                                        \
        float a = hs ? a##SLOT.y : a##SLOT.x;                                \
        uint2 u = u##SLOT;                                                   \
        AGG_LOAD(SLOT, i + 4)                                                \
        float w = __expf(lrelu(a + adh, NEG_GAT));                           \
        ssum += w;                                                           \
        float2 lo = __half22float2(*reinterpret_cast<__half2*>(&u.x));       \
        float2 hi = __half22float2(*reinterpret_cast<__half2*>(&u.y));       \
        acc.x = fmaf(lo.x, w, acc.x); acc.y = fmaf(lo.y, w, acc.y);          \
        acc.z = fmaf(hi.x, w, acc.z); acc.w = fmaf(hi.y, w, acc.w);          \
    }                                                                        \
    i++;                                                                     \
    if (i >= end) break;

__global__ void k_agg(const float* __restrict__ bias, float* __restrict__ out_ext,
                      int act, int use_ext) {
    int t = threadIdx.x, lane = t & 31;
    int n = blockIdx.x * 8 + (t >> 5);
    float2 adp = *(const float2*)(g_ald + n * 2);
    int hs = lane >> 4;
    float adh = hs ? adp.y : adp.x;
    int beg = g_rowptr[n], end = g_rowptr[n + 1];

    float4 acc = make_float4(0.f, 0.f, 0.f, 0.f);
    float ssum = 0.f;

    float2 aA = make_float2(0.f, 0.f), aB = aA, aC = aA, aD = aA;
    uint2 uA = make_uint2(0u, 0u), uB = uA, uC = uA, uD = uA;
    int i = beg;
    AGG_LOAD(A, i)
    AGG_LOAD(B, i + 1)
    AGG_LOAD(C, i + 2)
    AGG_LOAD(D, i + 3)
    while (i < end) {
        AGG_CONSUME(A)
        AGG_CONSUME(B)
        AGG_CONSUME(C)
        AGG_CONSUME(D)
    }
    float inv = 1.f / ssum;
    float4 b4 = __ldg((const float4*)bias + lane);
    float4 o4;
    o4.x = fmaf(acc.x, inv, b4.x); o4.y = fmaf(acc.y, inv, b4.y);
    o4.z = fmaf(acc.z, inv, b4.z); o4.w = fmaf(acc.w, inv, b4.w);
    if (act) {
        o4.x = lrelu(o4.x, NEG_ACT); o4.y = lrelu(o4.y, NEG_ACT);
        o4.z = lrelu(o4.z, NEG_ACT); o4.w = lrelu(o4.w, NEG_ACT);
    }
    float* out = use_ext ? out_ext : g_h1;
    ((float4*)(out + (size_t)n * DC))[lane] = o4;
}

// ---------------- gate MLP: 4 nodes/warp + fused exp/gsum ----------------
#define GT_STEP(COMP, ROWC)                                                        \
    {                                                                              \
        unsigned long long w;                                                      \
        lds_u64(w, sb + (((4 * k4 + ROWC) * 32 + lane) << 3));                     \
        float b0 = __shfl_sync(~0u, xv0.COMP, k4);                                 \
        float b1 = __shfl_sync(~0u, xv1.COMP, k4);                                 \
        float b2 = __shfl_sync(~0u, xv2.COMP, k4);                                 \
        float b3 = __shfl_sync(~0u, xv3.COMP, k4);                                 \
        pfma(ga0, pk2(b0), w);                                                     \
        pfma(ga1, pk2(b1), w);                                                     \
        pfma(ga2, pk2(b2), w);                                                     \
        pfma(ga3, pk2(b3), w);                                                     \
    }

__global__ void k_gate(const float* __restrict__ hout, const float* __restrict__ gw1,
                       const float* __restrict__ gb1, const float* __restrict__ gw2,
                       const float* __restrict__ gb2, const int* __restrict__ batch) {
    __shared__ float Gs[DC * Dd];  // 32 KB
    int t = threadIdx.x, lane = t & 31, warp = t >> 5;
    for (int i = t; i < DC * Dd; i += 256) Gs[i] = gw1[i];
    __syncthreads();
    unsigned sb = (unsigned)__cvta_generic_to_shared(Gs);
    int n0 = blockIdx.x * 32 + warp * 4;
    float4 xv0 = ((const float4*)(hout + (size_t)(n0 + 0) * DC))[lane];
    float4 xv1 = ((const float4*)(hout + (size_t)(n0 + 1) * DC))[lane];
    float4 xv2 = ((const float4*)(hout + (size_t)(n0 + 2) * DC))[lane];
    float4 xv3 = ((const float4*)(hout + (size_t)(n0 + 3) * DC))[lane];
    unsigned long long ga0 = 0, ga1 = 0, ga2 = 0, ga3 = 0;
    #pragma unroll
    for (int k4 = 0; k4 < 32; k4++) {
        GT_STEP(x, 0)
        GT_STEP(y, 1)
        GT_STEP(z, 2)
        GT_STEP(w, 3)
    }
    float2 gb = __ldg((const float2*)gb1 + lane);
    float2 gw = __ldg((const float2*)gw2 + lane);
    float gbias = __ldg(gb2);
    unsigned long long gas[4] = {ga0, ga1, ga2, ga3};
    #pragma unroll
    for (int qn = 0; qn < 4; qn++) {
        float2 f = upk(gas[qn]);
        float u0 = lrelu(f.x + gb.x, NEG_ACT);
        float u1 = lrelu(f.y + gb.y, NEG_ACT);
        float u = u0 * gw.x + u1 * gw.y;
        #pragma unroll
        for (int o = 16; o; o >>= 1) u += __shfl_xor_sync(~0u, u, o);
        if (lane == 0) {
            int n = n0 + qn;
            float ge = __expf(u + gbias);
            g_ge[n] = ge;
            atomicAdd(&g_gsum[batch[n]], ge);
        }
    }
}

// ---------------- segmented z aggregation (batch_idx is sorted) ----------------
#define ZCH 64
__global__ void k_zagg(const float* __restrict__ hout, float* __restrict__ zout,
                       const int* __restrict__ batch) {
    int t = threadIdx.x, lane = t & 31, warp = t >> 5;
    int w0 = blockIdx.x * 8 + warp;
    int n0 = w0 * ZCH;
    if (n0 >= Nn) return;
    int n1 = n0 + ZCH; if (n1 > Nn) n1 = Nn;
    float4 acc = make_float4(0.f, 0.f, 0.f, 0.f);
    int cg = batch[n0];
    for (int n = n0; n < n1; n++) {
        int g = batch[n];
        if (g != cg) {
            float* zb = zout + (size_t)cg * DC + lane * 4;
            atomicAdd(zb + 0, acc.x); atomicAdd(zb + 1, acc.y);
            atomicAdd(zb + 2, acc.z); atomicAdd(zb + 3, acc.w);
            acc = make_float4(0.f, 0.f, 0.f, 0.f);
            cg = g;
        }
        float w = g_ge[n] / g_gsum[g];
        float4 hv = ((const float4*)(hout + (size_t)n * DC))[lane];
        acc.x = fmaf(hv.x, w, acc.x); acc.y = fmaf(hv.y, w, acc.y);
        acc.z = fmaf(hv.z, w, acc.z); acc.w = fmaf(hv.w, w, acc.w);
    }
    float* zb = zout + (size_t)cg * DC + lane * 4;
    atomicAdd(zb + 0, acc.x); atomicAdd(zb + 1, acc.y);
    atomicAdd(zb + 2, acc.z); atomicAdd(zb + 3, acc.w);
}

// ---------------- launch ----------------
extern "C" void kernel_launch(void* const* d_in, const int* in_sizes, int n_in,
                              void* d_out, int out_size) {
    const int*   x     = (const int*)d_in[0];
    const int*   ei    = (const int*)d_in[1];
    const int*   batch = (const int*)d_in[2];
    const float* emb   = (const float*)d_in[3];
    const float* lng   = (const float*)d_in[4];
    const float* lnb   = (const float*)d_in[5];
    const float* W1    = (const float*)d_in[6];
    const float* as1   = (const float*)d_in[7];
    const float* ad1   = (const float*)d_in[8];
    const float* b1    = (const float*)d_in[9];
    const float* W2    = (const float*)d_in[10];
    const float* as2   = (const float*)d_in[11];
    const float* ad2   = (const float*)d_in[12];
    const float* b2    = (const float*)d_in[13];
    const float* gw1   = (const float*)d_in[14];
    const float* gb1   = (const float*)d_in[15];
    const float* gw2   = (const float*)d_in[16];
    const float* gb2   = (const float*)d_in[17];
    float* out  = (float*)d_out;
    float* zout = out + (size_t)Nn * DC;

    (void)in_sizes; (void)n_in; (void)out_size;

    k_zero<<<512, 256>>>(zout);
    k_count<<<(Ee / 4 + 255) / 256, 256>>>(ei);
    k_scan_local<<<NB_SCAN, 256>>>();
    k_scan_mid<<<1, 32>>>();
    k_scan_add<<<(Nn + 255) / 256, 256>>>();
    k_scatter<<<(Ee / 4 + Nn + 255) / 256, 256>>>(ei);
    k_embgemm1<<<(Nn + 31) / 32, 256>>>(x, emb, lng, lnb, W1, as1, ad1);
    k_agg<<<Nn / 8, 256>>>(b1, nullptr, 1, 0);            // -> g_h1 (fp32)
    k_gemm2<<<(Nn + 63) / 64, 256>>>(W2, as2, ad2);
    k_agg<<<Nn / 8, 256>>>(b2, out, 0, 1);                // -> d_out (h)
    k_gate<<<Nn / 32, 256>>>(out, gw1, gb1, gw2, gb2, batch);
    int zwarps = (Nn + ZCH - 1) / ZCH;
    k_zagg<<<(zwarps + 7) / 8, 256>>>(out, zout, batch);
}

// round 14
// speedup vs baseline: 1.0393x; 1.0393x over previous
#include <cuda_runtime.h>
#include <cuda_fp16.h>

#define Nn   100000
#define Ee   1600000
#define ETOT 1700000
#define Gg   1024
#define EMB  32
#define DC   128
#define Dd   64
#define LNEPS 1e-5f
#define NEG_GAT 0.2f
#define NEG_ACT 0.05f
#define NB_SCAN 98   // ceil(Nn/1024)

// ---------------- scratch ----------------
__device__ __half g_xwh[Nn * DC];       // 25.6 MB fp16 transformed feats (gather payload)
__device__ float g_h1[Nn * DC];         // 51.2 MB layer-1 output (fp32 for gemm2 accuracy)
__device__ float g_als[Nn * 2];
__device__ float g_ald[Nn * 2];
__device__ int   g_esrc[ETOT];
__device__ int   g_deg[Nn];
__device__ int   g_rowptr[Nn + 1];
__device__ int   g_cursor[Nn];
__device__ int   g_bsum[128];
__device__ int   g_bpre[128];
__device__ float g_ge[Nn];
__device__ float g_gsum[Gg];

__device__ __forceinline__ float lrelu(float x, float a) { return x >= 0.f ? x : a * x; }

// packed f32x2 helpers (Blackwell FFMA2)
__device__ __forceinline__ unsigned long long pk2(float b) {
    unsigned long long r;
    asm("mov.b64 %0, {%1, %1};" : "=l"(r) : "f"(b));
    return r;
}
__device__ __forceinline__ void pfma(unsigned long long& d, unsigned long long a, unsigned long long b) {
    asm("fma.rn.f32x2 %0, %1, %2, %0;" : "+l"(d) : "l"(a), "l"(b));
}
__device__ __forceinline__ float2 upk(unsigned long long v) {
    float2 f;
    asm("mov.b64 {%0, %1}, %2;" : "=f"(f.x), "=f"(f.y) : "l"(v));
    return f;
}
__device__ __forceinline__ void lds_v2u64(unsigned long long& lo, unsigned long long& hi, unsigned saddr) {
    asm volatile("ld.shared.v2.u64 {%0, %1}, [%2];" : "=l"(lo), "=l"(hi) : "r"(saddr));
}
__device__ __forceinline__ void lds_u64(unsigned long long& v, unsigned saddr) {
    asm volatile("ld.shared.u64 %0, [%1];" : "=l"(v) : "r"(saddr));
}

// store float4 as 4 halfs (8B) at row n, lane slot
__device__ __forceinline__ void st_h4(int n, int lane, float a, float b, float c, float d) {
    __half2 h01 = __floats2half2_rn(a, b);
    __half2 h23 = __floats2half2_rn(c, d);
    uint2 uv;
    uv.x = *reinterpret_cast<unsigned*>(&h01);
    uv.y = *reinterpret_cast<unsigned*>(&h23);
    ((uint2*)(g_xwh + (size_t)n * DC))[lane] = uv;
}

// ---------------- init ----------------
__global__ void k_zero(float* zout) {
    int i = blockIdx.x * blockDim.x + threadIdx.x;
    if (i < Nn) g_deg[i] = 1;   // self-loop contributes exactly 1 per node
    if (i < Gg) g_gsum[i] = 0.f;
    if (i < Gg * DC) zout[i] = 0.f;
}

// ---------------- CSR build ----------------
// count only real edges (self-loops pre-counted in k_zero), int4 loads
__global__ void k_count(const int* __restrict__ ei) {
    int i = blockIdx.x * blockDim.x + threadIdx.x;   // i indexes groups of 4
    if (i >= Ee / 4) return;
    int4 d4 = ((const int4*)(ei + Ee))[i];
    atomicAdd(&g_deg[d4.x], 1);
    atomicAdd(&g_deg[d4.y], 1);
    atomicAdd(&g_deg[d4.z], 1);
    atomicAdd(&g_deg[d4.w], 1);
}

__global__ void k_scan_local() {
    __shared__ int wsum[8];
    int t = threadIdx.x, lane = t & 31, warp = t >> 5;
    int base = blockIdx.x * 1024 + t * 4;
    int v0 = (base + 0 < Nn) ? g_deg[base + 0] : 0;
    int v1 = (base + 1 < Nn) ? g_deg[base + 1] : 0;
    int v2 = (base + 2 < Nn) ? g_deg[base + 2] : 0;
    int v3 = (base + 3 < Nn) ? g_deg[base + 3] : 0;
    int s = v0 + v1 + v2 + v3;
    int inc = s;
    #pragma unroll
    for (int o = 1; o < 32; o <<= 1) {
        int x = __shfl_up_sync(~0u, inc, o);
        if (lane >= o) inc += x;
    }
    if (lane == 31) wsum[warp] = inc;
    __syncthreads();
    if (t < 8) {
        int ws = wsum[t];
        #pragma unroll
        for (int o = 1; o < 8; o <<= 1) {
            int x = __shfl_up_sync(0xffu, ws, o);
            if (t >= o) ws += x;
        }
        wsum[t] = ws;
        if (t == 7) g_bsum[blockIdx.x] = ws;
    }
    __syncthreads();
    int warpoff = warp ? wsum[warp - 1] : 0;
    int e0 = warpoff + inc - s;
    int e1 = e0 + v0, e2 = e1 + v1, e3 = e2 + v2;
    if (base + 0 < Nn) g_rowptr[base + 0] = e0;
    if (base + 1 < Nn) g_rowptr[base + 1] = e1;
    if (base + 2 < Nn) g_rowptr[base + 2] = e2;
    if (base + 3 < Nn) g_rowptr[base + 3] = e3;
}

__global__ void k_scan_mid() {
    int lane = threadIdx.x;
    int base = lane * 4;
    int v0 = (base + 0 < NB_SCAN) ? g_bsum[base + 0] : 0;
    int v1 = (base + 1 < NB_SCAN) ? g_bsum[base + 1] : 0;
    int v2 = (base + 2 < NB_SCAN) ? g_bsum[base + 2] : 0;
    int v3 = (base + 3 < NB_SCAN) ? g_bsum[base + 3] : 0;
    int s = v0 + v1 + v2 + v3;
    int inc = s;
    #pragma unroll
    for (int o = 1; o < 32; o <<= 1) {
        int x = __shfl_up_sync(~0u, inc, o);
        if (lane >= o) inc += x;
    }
    int e0 = inc - s;
    int e1 = e0 + v0, e2 = e1 + v1, e3 = e2 + v2;
    if (base + 0 < 128) g_bpre[base + 0] = e0;
    if (base + 1 < 128) g_bpre[base + 1] = e1;
    if (base + 2 < 128) g_bpre[base + 2] = e2;
    if (base + 3 < 128) g_bpre[base + 3] = e3;
    if (lane == 31) g_rowptr[Nn] = inc;
}

__global__ void k_scan_add() {
    int i = blockIdx.x * blockDim.x + threadIdx.x;
    if (i >= Nn) return;
    int r = g_rowptr[i] + g_bpre[i >> 10];
    g_rowptr[i] = r;
    g_cursor[i] = r;
}

// vectorized scatter: 4 real edges/thread; tail threads place self-loops
__global__ void k_scatter(const int* __restrict__ ei) {
    int i = blockIdx.x * blockDim.x + threadIdx.x;
    if (i < Ee / 4) {
        int4 s4 = ((const int4*)ei)[i];
        int4 d4 = ((const int4*)(ei + Ee))[i];
        g_esrc[atomicAdd(&g_cursor[d4.x], 1)] = s4.x;
        g_esrc[atomicAdd(&g_cursor[d4.y], 1)] = s4.y;
        g_esrc[atomicAdd(&g_cursor[d4.z], 1)] = s4.z;
        g_esrc[atomicAdd(&g_cursor[d4.w], 1)] = s4.w;
    } else {
        int n = i - Ee / 4;
        if (n < Nn) g_esrc[atomicAdd(&g_cursor[n], 1)] = n;
    }
}

// ---------------- fused embed + LN + GEMM 32->128, 4 nodes/warp, pfma ----------------
__global__ void __launch_bounds__(256) k_embgemm1(
        const int* __restrict__ x, const float* __restrict__ emb,
        const float* __restrict__ lng, const float* __restrict__ lnb,
        const float* __restrict__ W1, const float* __restrict__ asrc,
        const float* __restrict__ adst) {
    __shared__ float Ws[EMB * DC];  // 16 KB
    int t = threadIdx.x, lane = t & 31, warp = t >> 5;
    for (int i = t; i < EMB * DC; i += 256) Ws[i] = W1[i];
    __syncthreads();
    unsigned sb = (unsigned)__cvta_generic_to_shared(Ws);
    int n0 = blockIdx.x * 32 + warp * 4;
    float lg = lng[lane], lb = lnb[lane];
    float xv[4];
    #pragma unroll
    for (int q = 0; q < 4; q++) {
        int n = n0 + q;
        int v = (n < Nn) ? x[n] : 0;
        float val = emb[v * EMB + lane];
        float s = val;
        #pragma unroll
        for (int o = 16; o; o >>= 1) s += __shfl_xor_sync(~0u, s, o);
        float mu = s * (1.f / EMB);
        float d = val - mu;
        float qq = d * d;
        #pragma unroll
        for (int o = 16; o; o >>= 1) qq += __shfl_xor_sync(~0u, qq, o);
        xv[q] = d * rsqrtf(qq * (1.f / EMB) + LNEPS) * lg + lb;
    }
    unsigned long long ac[4][2];
    #pragma unroll
    for (int q = 0; q < 4; q++) { ac[q][0] = 0; ac[q][1] = 0; }
    #pragma unroll
    for (int k = 0; k < 32; k++) {
        unsigned long long wlo, whi;
        lds_v2u64(wlo, whi, sb + ((k * 32 + lane) << 4));
        #pragma unroll
        for (int q = 0; q < 4; q++) {
            float b = __shfl_sync(~0u, xv[q], k);
            unsigned long long p = pk2(b);
            pfma(ac[q][0], p, wlo);
            pfma(ac[q][1], p, whi);
        }
    }
    float4 as = __ldg((const float4*)asrc + lane);
    float4 ad = __ldg((const float4*)adst + lane);
    #pragma unroll
    for (int q = 0; q < 4; q++) {
        int n = n0 + q;
        float2 lo = upk(ac[q][0]), hi = upk(ac[q][1]);
        float ps = lo.x * as.x + lo.y * as.y + hi.x * as.z + hi.y * as.w;
        float pd = lo.x * ad.x + lo.y * ad.y + hi.x * ad.z + hi.y * ad.w;
        #pragma unroll
        for (int o = 8; o; o >>= 1) {
            ps += __shfl_xor_sync(~0u, ps, o);
            pd += __shfl_xor_sync(~0u, pd, o);
        }
        if (n < Nn) {
            st_h4(n, lane, lo.x, lo.y, hi.x, hi.y);
            if ((lane & 15) == 0) {
                int h = lane >> 4;
                g_als[n * 2 + h] = ps;
                g_ald[n * 2 + h] = pd;
            }
        }
    }
}

// ---------------- GEMM 128->128, 8 nodes/warp, packed f32x2 ----------------
__global__ void __launch_bounds__(256) k_gemm2(const float* __restrict__ W2,
                                               const float* __restrict__ asrc,
                                               const float* __restrict__ adst) {
    __shared__ float Ws[64 * DC];  // 32 KB
    int t = threadIdx.x, lane = t & 31, warp = t >> 5;
    unsigned sb = (unsigned)__cvta_generic_to_shared(Ws);
    int n0 = blockIdx.x * 64 + warp * 8;
    float xv[8][4];
    unsigned long long ac[8][2];
    #pragma unroll
    for (int q = 0; q < 8; q++) {
        int nq = n0 + q; if (nq > Nn - 1) nq = Nn - 1;
        float4 r = ((const float4*)(g_h1 + (size_t)nq * DC))[lane];
        xv[q][0] = r.x; xv[q][1] = r.y; xv[q][2] = r.z; xv[q][3] = r.w;
        ac[q][0] = 0; ac[q][1] = 0;
    }
    for (int ph = 0; ph < 2; ++ph) {
        __syncthreads();
        for (int i = t; i < 64 * DC; i += 256) Ws[i] = W2[ph * 64 * DC + i];
        __syncthreads();
        #pragma unroll
        for (int k4 = 0; k4 < 16; k4++) {
            int ksel = ph * 16 + k4;
            #pragma unroll
            for (int c = 0; c < 4; c++) {
                unsigned long long wlo, whi;
                lds_v2u64(wlo, whi, sb + (((4 * k4 + c) * 32 + lane) << 4));
                #pragma unroll
                for (int q = 0; q < 8; q++) {
                    float b = __shfl_sync(~0u, xv[q][c], ksel);
                    unsigned long long p = pk2(b);
                    pfma(ac[q][0], p, wlo);
                    pfma(ac[q][1], p, whi);
                }
            }
        }
    }
    float4 as = __ldg((const float4*)asrc + lane);
    float4 ad = __ldg((const float4*)adst + lane);
    #pragma unroll
    for (int q = 0; q < 8; q++) {
        int n = n0 + q;
        float2 lo = upk(ac[q][0]), hi = upk(ac[q][1]);
        float ps = lo.x * as.x + lo.y * as.y + hi.x * as.z + hi.y * as.w;
        float pd = lo.x * ad.x + lo.y * ad.y + hi.x * ad.z + hi.y * ad.w;
        #pragma unroll
        for (int o = 8; o; o >>= 1) {
            ps += __shfl_xor_sync(~0u, ps, o);
            pd += __shfl_xor_sync(~0u, pd, o);
        }
        if (n < Nn) {
            st_h4(n, lane, lo.x, lo.y, hi.x, hi.y);
            if ((lane & 15) == 0) {
                int h = lane >> 4;
                g_als[n * 2 + h] = ps;
                g_ald[n * 2 + h] = pd;
            }
        }
    }
}

// ---------------- GAT aggregation: depth-2 pipeline (R9 known-good), fp16 gather ----------------
__global__ void k_agg(const float* __restrict__ bias, float* __restrict__ out_ext,
                      int act, int use_ext) {
    int t = threadIdx.x, lane = t & 31;
    int n = blockIdx.x * 8 + (t >> 5);
    float2 adp = *(const float2*)(g_ald + n * 2);
    int hs = lane >> 4;
    float adh = hs ? adp.y : adp.x;
    int beg = g_rowptr[n], end = g_rowptr[n + 1];

    float4 acc = make_float4(0.f, 0.f, 0.f, 0.f);
    float ssum = 0.f;

    // two-slot software pipeline: slots hold edges i (A) and i+1 (B)
    float aA = 0.f, aB = 0.f;
    uint2 uA = make_uint2(0u, 0u), uB = make_uint2(0u, 0u);
    int i = beg;
    if (i < end) {
        int s = g_esrc[i];
        aA = g_als[2 * s + hs];
        uA = ((const uint2*)(g_xwh + (size_t)s * DC))[lane];
    }
    if (i + 1 < end) {
        int s = g_esrc[i + 1];
        aB = g_als[2 * s + hs];
        uB = ((const uint2*)(g_xwh + (size_t)s * DC))[lane];
    }
    while (i < end) {
        // consume slot A (edge i), refill with edge i+2
        {
            float a = aA; uint2 u = uA;
            if (i + 2 < end) {
                int s = g_esrc[i + 2];
                aA = g_als[2 * s + hs];
                uA = ((const uint2*)(g_xwh + (size_t)s * DC))[lane];
            }
            float w = __expf(lrelu(a + adh, NEG_GAT));
            ssum += w;
            float2 lo = __half22float2(*reinterpret_cast<__half2*>(&u.x));
            float2 hi = __half22float2(*reinterpret_cast<__half2*>(&u.y));
            acc.x = fmaf(lo.x, w, acc.x); acc.y = fmaf(lo.y, w, acc.y);
            acc.z = fmaf(hi.x, w, acc.z); acc.w = fmaf(hi.y, w, acc.w);
        }
        i++;
        if (i >= end) break;
        // consume slot B (edge i), refill with edge i+2
        {
            float a = aB; uint2 u = uB;
            if (i + 2 < end) {
                int s = g_esrc[i + 2];
                aB = g_als[2 * s + hs];
                uB = ((const uint2*)(g_xwh + (size_t)s * DC))[lane];
            }
            float w = __expf(lrelu(a + adh, NEG_GAT));
            ssum += w;
            float2 lo = __half22float2(*reinterpret_cast<__half2*>(&u.x));
            float2 hi = __half22float2(*reinterpret_cast<__half2*>(&u.y));
            acc.x = fmaf(lo.x, w, acc.x); acc.y = fmaf(lo.y, w, acc.y);
            acc.z = fmaf(hi.x, w, acc.z); acc.w = fmaf(hi.y, w, acc.w);
        }
        i++;
    }
    float inv = 1.f / ssum;
    float4 b4 = __ldg((const float4*)bias + lane);
    float4 o4;
    o4.x = fmaf(acc.x, inv, b4.x); o4.y = fmaf(acc.y, inv, b4.y);
    o4.z = fmaf(acc.z, inv, b4.z); o4.w = fmaf(acc.w, inv, b4.w);
    if (act) {
        o4.x = lrelu(o4.x, NEG_ACT); o4.y = lrelu(o4.y, NEG_ACT);
        o4.z = lrelu(o4.z, NEG_ACT); o4.w = lrelu(o4.w, NEG_ACT);
    }
    float* out = use_ext ? out_ext : g_h1;
    ((float4*)(out + (size_t)n * DC))[lane] = o4;
}

// ---------------- gate MLP: 4 nodes/warp + fused exp/gsum ----------------
#define GT_STEP(COMP, ROWC)                                                        \
    {                                                                              \
        unsigned long long w;                                                      \
        lds_u64(w, sb + (((4 * k4 + ROWC) * 32 + lane) << 3));                     \
        float b0 = __shfl_sync(~0u, xv0.COMP, k4);                                 \
        float b1 = __shfl_sync(~0u, xv1.COMP, k4);                                 \
        float b2 = __shfl_sync(~0u, xv2.COMP, k4);                                 \
        float b3 = __shfl_sync(~0u, xv3.COMP, k4);                                 \
        pfma(ga0, pk2(b0), w);                                                     \
        pfma(ga1, pk2(b1), w);                                                     \
        pfma(ga2, pk2(b2), w);                                                     \
        pfma(ga3, pk2(b3), w);                                                     \
    }

__global__ void k_gate(const float* __restrict__ hout, const float* __restrict__ gw1,
                       const float* __restrict__ gb1, const float* __restrict__ gw2,
                       const float* __restrict__ gb2, const int* __restrict__ batch) {
    __shared__ float Gs[DC * Dd];  // 32 KB
    int t = threadIdx.x, lane = t & 31, warp = t >> 5;
    for (int i = t; i < DC * Dd; i += 256) Gs[i] = gw1[i];
    __syncthreads();
    unsigned sb = (unsigned)__cvta_generic_to_shared(Gs);
    int n0 = blockIdx.x * 32 + warp * 4;
    float4 xv0 = ((const float4*)(hout + (size_t)(n0 + 0) * DC))[lane];
    float4 xv1 = ((const float4*)(hout + (size_t)(n0 + 1) * DC))[lane];
    float4 xv2 = ((const float4*)(hout + (size_t)(n0 + 2) * DC))[lane];
    float4 xv3 = ((const float4*)(hout + (size_t)(n0 + 3) * DC))[lane];
    unsigned long long ga0 = 0, ga1 = 0, ga2 = 0, ga3 = 0;
    #pragma unroll
    for (int k4 = 0; k4 < 32; k4++) {
        GT_STEP(x, 0)
        GT_STEP(y, 1)
        GT_STEP(z, 2)
        GT_STEP(w, 3)
    }
    float2 gb = __ldg((const float2*)gb1 + lane);
    float2 gw = __ldg((const float2*)gw2 + lane);
    float gbias = __ldg(gb2);
    unsigned long long gas[4] = {ga0, ga1, ga2, ga3};
    #pragma unroll
    for (int qn = 0; qn < 4; qn++) {
        float2 f = upk(gas[qn]);
        float u0 = lrelu(f.x + gb.x, NEG_ACT);
        float u1 = lrelu(f.y + gb.y, NEG_ACT);
        float u = u0 * gw.x + u1 * gw.y;
        #pragma unroll
        for (int o = 16; o; o >>= 1) u += __shfl_xor_sync(~0u, u, o);
        if (lane == 0) {
            int n = n0 + qn;
            float ge = __expf(u + gbias);
            g_ge[n] = ge;
            atomicAdd(&g_gsum[batch[n]], ge);
        }
    }
}

// ---------------- segmented z aggregation (batch_idx is sorted) ----------------
#define ZCH 64
__global__ void k_zagg(const float* __restrict__ hout, float* __restrict__ zout,
                       const int* __restrict__ batch) {
    int t = threadIdx.x, lane = t & 31, warp = t >> 5;
    int w0 = blockIdx.x * 8 + warp;
    int n0 = w0 * ZCH;
    if (n0 >= Nn) return;
    int n1 = n0 + ZCH; if (n1 > Nn) n1 = Nn;
    float4 acc = make_float4(0.f, 0.f, 0.f, 0.f);
    int cg = batch[n0];
    for (int n = n0; n < n1; n++) {
        int g = batch[n];
        if (g != cg) {
            float* zb = zout + (size_t)cg * DC + lane * 4;
            atomicAdd(zb + 0, acc.x); atomicAdd(zb + 1, acc.y);
            atomicAdd(zb + 2, acc.z); atomicAdd(zb + 3, acc.w);
            acc = make_float4(0.f, 0.f, 0.f, 0.f);
            cg = g;
        }
        float w = g_ge[n] / g_gsum[g];
        float4 hv = ((const float4*)(hout + (size_t)n * DC))[lane];
        acc.x = fmaf(hv.x, w, acc.x); acc.y = fmaf(hv.y, w, acc.y);
        acc.z = fmaf(hv.z, w, acc.z); acc.w = fmaf(hv.w, w, acc.w);
    }
    float* zb = zout + (size_t)cg * DC + lane * 4;
    atomicAdd(zb + 0, acc.x); atomicAdd(zb + 1, acc.y);
    atomicAdd(zb + 2, acc.z); atomicAdd(zb + 3, acc.w);
}

// ---------------- launch (two-stream overlap: CSR build || embgemm1) ----------------
extern "C" void kernel_launch(void* const* d_in, const int* in_sizes, int n_in,
                              void* d_out, int out_size) {
    const int*   x     = (const int*)d_in[0];
    const int*   ei    = (const int*)d_in[1];
    const int*   batch = (const int*)d_in[2];
    const float* emb   = (const float*)d_in[3];
    const float* lng   = (const float*)d_in[4];
    const float* lnb   = (const float*)d_in[5];
    const float* W1    = (const float*)d_in[6];
    const float* as1   = (const float*)d_in[7];
    const float* ad1   = (const float*)d_in[8];
    const float* b1    = (const float*)d_in[9];
    const float* W2    = (const float*)d_in[10];
    const float* as2   = (const float*)d_in[11];
    const float* ad2   = (const float*)d_in[12];
    const float* b2    = (const float*)d_in[13];
    const float* gw1   = (const float*)d_in[14];
    const float* gb1   = (const float*)d_in[15];
    const float* gw2   = (const float*)d_in[16];
    const float* gb2   = (const float*)d_in[17];
    float* out  = (float*)d_out;
    float* zout = out + (size_t)Nn * DC;

    (void)in_sizes; (void)n_in; (void)out_size;

    // one-time handle creation (same work enqueued on every call)
    static cudaStream_t s1 = nullptr;
    static cudaEvent_t evFork = nullptr, evJoin = nullptr;
    if (s1 == nullptr) {
        cudaStreamCreateWithFlags(&s1, cudaStreamNonBlocking);
        cudaEventCreateWithFlags(&evFork, cudaEventDisableTiming);
        cudaEventCreateWithFlags(&evJoin, cudaEventDisableTiming);
    }

    cudaStream_t s0 = 0;  // capture-origin (legacy) stream

    k_zero<<<512, 256, 0, s0>>>(zout);            // inits g_deg, g_gsum, zout
    cudaEventRecord(evFork, s0);
    cudaStreamWaitEvent(s1, evFork, 0);

    // CSR build chain on side stream
    k_count<<<(Ee / 4 + 255) / 256, 256, 0, s1>>>(ei);
    k_scan_local<<<NB_SCAN, 256, 0, s1>>>();
    k_scan_mid<<<1, 32, 0, s1>>>();
    k_scan_add<<<(Nn + 255) / 256, 256, 0, s1>>>();
    k_scatter<<<(Ee / 4 + Nn + 255) / 256, 256, 0, s1>>>(ei);
    cudaEventRecord(evJoin, s1);

    // independent dense work on main stream (overlaps CSR build)
    k_embgemm1<<<(Nn + 31) / 32, 256, 0, s0>>>(x, emb, lng, lnb, W1, as1, ad1);

    cudaStreamWaitEvent(s0, evJoin, 0);

    k_agg<<<Nn / 8, 256, 0, s0>>>(b1, nullptr, 1, 0);      // -> g_h1 (fp32)
    k_gemm2<<<(Nn + 63) / 64, 256, 0, s0>>>(W2, as2, ad2);
    k_agg<<<Nn / 8, 256, 0, s0>>>(b2, out, 0, 1);          // -> d_out (h)
    k_gate<<<Nn / 32, 256, 0, s0>>>(out, gw1, gb1, gw2, gb2, batch);
    int zwarps = (Nn + ZCH - 1) / ZCH;
    k_zagg<<<(zwarps + 7) / 8, 256, 0, s0>>>(out, zout, batch);
}

// round 15
// speedup vs baseline: 1.0650x; 1.0247x over previous
#include <cuda_runtime.h>
#include <cuda_fp16.h>

#define Nn   100000
#define Ee   1600000
#define ETOT 1700000
#define Gg   1024
#define EMB  32
#define DC   128
#define Dd   64
#define LNEPS 1e-5f
#define NEG_GAT 0.2f
#define NEG_ACT 0.05f
#define NB_SCAN 98   // ceil(Nn/1024)

// ---------------- scratch ----------------
__device__ __half g_xwh[Nn * DC];       // 25.6 MB fp16 transformed feats (gather payload)
__device__ __half g_h1h[Nn * DC];       // 25.6 MB fp16 layer-1 output (gemm2 input)
__device__ float g_als[Nn * 2];
__device__ float g_ald[Nn * 2];
__device__ int   g_esrc[ETOT];
__device__ int   g_deg[Nn];
__device__ int   g_rowptr[Nn + 1];
__device__ int   g_cursor[Nn];
__device__ int   g_bsum[128];
__device__ int   g_bpre[128];
__device__ float g_ge[Nn];
__device__ float g_gsum[Gg];

__device__ __forceinline__ float lrelu(float x, float a) { return x >= 0.f ? x : a * x; }

// packed f32x2 helpers (Blackwell FFMA2)
__device__ __forceinline__ unsigned long long pk2(float b) {
    unsigned long long r;
    asm("mov.b64 %0, {%1, %1};" : "=l"(r) : "f"(b));
    return r;
}
__device__ __forceinline__ void pfma(unsigned long long& d, unsigned long long a, unsigned long long b) {
    asm("fma.rn.f32x2 %0, %1, %2, %0;" : "+l"(d) : "l"(a), "l"(b));
}
__device__ __forceinline__ float2 upk(unsigned long long v) {
    float2 f;
    asm("mov.b64 {%0, %1}, %2;" : "=f"(f.x), "=f"(f.y) : "l"(v));
    return f;
}
__device__ __forceinline__ void lds_v2u64(unsigned long long& lo, unsigned long long& hi, unsigned saddr) {
    asm volatile("ld.shared.v2.u64 {%0, %1}, [%2];" : "=l"(lo), "=l"(hi) : "r"(saddr));
}
__device__ __forceinline__ void lds_u64(unsigned long long& v, unsigned saddr) {
    asm volatile("ld.shared.u64 %0, [%1];" : "=l"(v) : "r"(saddr));
}

// store float4 as 4 halfs (8B) at row n, lane slot, into an arbitrary half table
__device__ __forceinline__ void st_h4t(__half* tab, int n, int lane, float a, float b, float c, float d) {
    __half2 h01 = __floats2half2_rn(a, b);
    __half2 h23 = __floats2half2_rn(c, d);
    uint2 uv;
    uv.x = *reinterpret_cast<unsigned*>(&h01);
    uv.y = *reinterpret_cast<unsigned*>(&h23);
    ((uint2*)(tab + (size_t)n * DC))[lane] = uv;
}

// ---------------- init ----------------
__global__ void k_zero(float* zout) {
    int i = blockIdx.x * blockDim.x + threadIdx.x;
    if (i < Nn) g_deg[i] = 1;   // self-loop contributes exactly 1 per node
    if (i < Gg) g_gsum[i] = 0.f;
    if (i < Gg * DC) zout[i] = 0.f;
}

// ---------------- CSR build ----------------
__global__ void k_count(const int* __restrict__ ei) {
    int i = blockIdx.x * blockDim.x + threadIdx.x;   // i indexes groups of 4
    if (i >= Ee / 4) return;
    int4 d4 = ((const int4*)(ei + Ee))[i];
    atomicAdd(&g_deg[d4.x], 1);
    atomicAdd(&g_deg[d4.y], 1);
    atomicAdd(&g_deg[d4.z], 1);
    atomicAdd(&g_deg[d4.w], 1);
}

__global__ void k_scan_local() {
    __shared__ int wsum[8];
    int t = threadIdx.x, lane = t & 31, warp = t >> 5;
    int base = blockIdx.x * 1024 + t * 4;
    int v0 = (base + 0 < Nn) ? g_deg[base + 0] : 0;
    int v1 = (base + 1 < Nn) ? g_deg[base + 1] : 0;
    int v2 = (base + 2 < Nn) ? g_deg[base + 2] : 0;
    int v3 = (base + 3 < Nn) ? g_deg[base + 3] : 0;
    int s = v0 + v1 + v2 + v3;
    int inc = s;
    #pragma unroll
    for (int o = 1; o < 32; o <<= 1) {
        int x = __shfl_up_sync(~0u, inc, o);
        if (lane >= o) inc += x;
    }
    if (lane == 31) wsum[warp] = inc;
    __syncthreads();
    if (t < 8) {
        int ws = wsum[t];
        #pragma unroll
        for (int o = 1; o < 8; o <<= 1) {
            int x = __shfl_up_sync(0xffu, ws, o);
            if (t >= o) ws += x;
        }
        wsum[t] = ws;
        if (t == 7) g_bsum[blockIdx.x] = ws;
    }
    __syncthreads();
    int warpoff = warp ? wsum[warp - 1] : 0;
    int e0 = warpoff + inc - s;
    int e1 = e0 + v0, e2 = e1 + v1, e3 = e2 + v2;
    if (base + 0 < Nn) g_rowptr[base + 0] = e0;
    if (base + 1 < Nn) g_rowptr[base + 1] = e1;
    if (base + 2 < Nn) g_rowptr[base + 2] = e2;
    if (base + 3 < Nn) g_rowptr[base + 3] = e3;
}

__global__ void k_scan_mid() {
    int lane = threadIdx.x;
    int base = lane * 4;
    int v0 = (base + 0 < NB_SCAN) ? g_bsum[base + 0] : 0;
    int v1 = (base + 1 < NB_SCAN) ? g_bsum[base + 1] : 0;
    int v2 = (base + 2 < NB_SCAN) ? g_bsum[base + 2] : 0;
    int v3 = (base + 3 < NB_SCAN) ? g_bsum[base + 3] : 0;
    int s = v0 + v1 + v2 + v3;
    int inc = s;
    #pragma unroll
    for (int o = 1; o < 32; o <<= 1) {
        int x = __shfl_up_sync(~0u, inc, o);
        if (lane >= o) inc += x;
    }
    int e0 = inc - s;
    int e1 = e0 + v0, e2 = e1 + v1, e3 = e2 + v2;
    if (base + 0 < 128) g_bpre[base + 0] = e0;
    if (base + 1 < 128) g_bpre[base + 1] = e1;
    if (base + 2 < 128) g_bpre[base + 2] = e2;
    if (base + 3 < 128) g_bpre[base + 3] = e3;
    if (lane == 31) g_rowptr[Nn] = inc;
}

__global__ void k_scan_add() {
    int i = blockIdx.x * blockDim.x + threadIdx.x;
    if (i >= Nn) return;
    int r = g_rowptr[i] + g_bpre[i >> 10];
    g_rowptr[i] = r;
    g_cursor[i] = r;
}

__global__ void k_scatter(const int* __restrict__ ei) {
    int i = blockIdx.x * blockDim.x + threadIdx.x;
    if (i < Ee / 4) {
        int4 s4 = ((const int4*)ei)[i];
        int4 d4 = ((const int4*)(ei + Ee))[i];
        g_esrc[atomicAdd(&g_cursor[d4.x], 1)] = s4.x;
        g_esrc[atomicAdd(&g_cursor[d4.y], 1)] = s4.y;
        g_esrc[atomicAdd(&g_cursor[d4.z], 1)] = s4.z;
        g_esrc[atomicAdd(&g_cursor[d4.w], 1)] = s4.w;
    } else {
        int n = i - Ee / 4;
        if (n < Nn) g_esrc[atomicAdd(&g_cursor[n], 1)] = n;
    }
}

// ---------------- fused embed + LN + GEMM 32->128, 4 nodes/warp, pfma ----------------
__global__ void __launch_bounds__(256) k_embgemm1(
        const int* __restrict__ x, const float* __restrict__ emb,
        const float* __restrict__ lng, const float* __restrict__ lnb,
        const float* __restrict__ W1, const float* __restrict__ asrc,
        const float* __restrict__ adst) {
    __shared__ float Ws[EMB * DC];  // 16 KB
    int t = threadIdx.x, lane = t & 31, warp = t >> 5;
    for (int i = t; i < EMB * DC; i += 256) Ws[i] = W1[i];
    __syncthreads();
    unsigned sb = (unsigned)__cvta_generic_to_shared(Ws);
    int n0 = blockIdx.x * 32 + warp * 4;
    float lg = lng[lane], lb = lnb[lane];
    float xv[4];
    #pragma unroll
    for (int q = 0; q < 4; q++) {
        int n = n0 + q;
        int v = (n < Nn) ? x[n] : 0;
        float val = emb[v * EMB + lane];
        float s = val;
        #pragma unroll
        for (int o = 16; o; o >>= 1) s += __shfl_xor_sync(~0u, s, o);
        float mu = s * (1.f / EMB);
        float d = val - mu;
        float qq = d * d;
        #pragma unroll
        for (int o = 16; o; o >>= 1) qq += __shfl_xor_sync(~0u, qq, o);
        xv[q] = d * rsqrtf(qq * (1.f / EMB) + LNEPS) * lg + lb;
    }
    unsigned long long ac[4][2];
    #pragma unroll
    for (int q = 0; q < 4; q++) { ac[q][0] = 0; ac[q][1] = 0; }
    #pragma unroll
    for (int k = 0; k < 32; k++) {
        unsigned long long wlo, whi;
        lds_v2u64(wlo, whi, sb + ((k * 32 + lane) << 4));
        #pragma unroll
        for (int q = 0; q < 4; q++) {
            float b = __shfl_sync(~0u, xv[q], k);
            unsigned long long p = pk2(b);
            pfma(ac[q][0], p, wlo);
            pfma(ac[q][1], p, whi);
        }
    }
    float4 as = __ldg((const float4*)asrc + lane);
    float4 ad = __ldg((const float4*)adst + lane);
    #pragma unroll
    for (int q = 0; q < 4; q++) {
        int n = n0 + q;
        float2 lo = upk(ac[q][0]), hi = upk(ac[q][1]);
        float ps = lo.x * as.x + lo.y * as.y + hi.x * as.z + hi.y * as.w;
        float pd = lo.x * ad.x + lo.y * ad.y + hi.x * ad.z + hi.y * ad.w;
        #pragma unroll
        for (int o = 8; o; o >>= 1) {
            ps += __shfl_xor_sync(~0u, ps, o);
            pd += __shfl_xor_sync(~0u, pd, o);
        }
        if (n < Nn) {
            st_h4t(g_xwh, n, lane, lo.x, lo.y, hi.x, hi.y);
            if ((lane & 15) == 0) {
                int h = lane >> 4;
                g_als[n * 2 + h] = ps;
                g_ald[n * 2 + h] = pd;
            }
        }
    }
}

// ---------------- GEMM 128->128, 8 nodes/warp, fp16 input, packed f32x2 ----------------
__global__ void __launch_bounds__(256) k_gemm2(const float* __restrict__ W2,
                                               const float* __restrict__ asrc,
                                               const float* __restrict__ adst) {
    __shared__ float Ws[64 * DC];  // 32 KB
    int t = threadIdx.x, lane = t & 31, warp = t >> 5;
    unsigned sb = (unsigned)__cvta_generic_to_shared(Ws);
    int n0 = blockIdx.x * 64 + warp * 8;
    float xv[8][4];
    unsigned long long ac[8][2];
    #pragma unroll
    for (int q = 0; q < 8; q++) {
        int nq = n0 + q; if (nq > Nn - 1) nq = Nn - 1;
        uint2 uv = ((const uint2*)(g_h1h + (size_t)nq * DC))[lane];
        float2 lo = __half22float2(*reinterpret_cast<__half2*>(&uv.x));
        float2 hi = __half22float2(*reinterpret_cast<__half2*>(&uv.y));
        xv[q][0] = lo.x; xv[q][1] = lo.y; xv[q][2] = hi.x; xv[q][3] = hi.y;
        ac[q][0] = 0; ac[q][1] = 0;
    }
    for (int ph = 0; ph < 2; ++ph) {
        __syncthreads();
        for (int i = t; i < 64 * DC; i += 256) Ws[i] = W2[ph * 64 * DC + i];
        __syncthreads();
        #pragma unroll
        for (int k4 = 0; k4 < 16; k4++) {
            int ksel = ph * 16 + k4;
            #pragma unroll
            for (int c = 0; c < 4; c++) {
                unsigned long long wlo, whi;
                lds_v2u64(wlo, whi, sb + (((4 * k4 + c) * 32 + lane) << 4));
                #pragma unroll
                for (int q = 0; q < 8; q++) {
                    float b = __shfl_sync(~0u, xv[q][c], ksel);
                    unsigned long long p = pk2(b);
                    pfma(ac[q][0], p, wlo);
                    pfma(ac[q][1], p, whi);
                }
            }
        }
    }
    float4 as = __ldg((const float4*)asrc + lane);
    float4 ad = __ldg((const float4*)adst + lane);
    #pragma unroll
    for (int q = 0; q < 8; q++) {
        int n = n0 + q;
        float2 lo = upk(ac[q][0]), hi = upk(ac[q][1]);
        float ps = lo.x * as.x + lo.y * as.y + hi.x * as.z + hi.y * as.w;
        float pd = lo.x * ad.x + lo.y * ad.y + hi.x * ad.z + hi.y * ad.w;
        #pragma unroll
        for (int o = 8; o; o >>= 1) {
            ps += __shfl_xor_sync(~0u, ps, o);
            pd += __shfl_xor_sync(~0u, pd, o);
        }
        if (n < Nn) {
            st_h4t(g_xwh, n, lane, lo.x, lo.y, hi.x, hi.y);
            if ((lane & 15) == 0) {
                int h = lane >> 4;
                g_als[n * 2 + h] = ps;
                g_ald[n * 2 + h] = pd;
            }
        }
    }
}

// ---------------- GAT aggregation: depth-2 pipeline, fp16 gather ----------------
// act!=0: layer-1 -> write fp16 to g_h1h.  act==0: layer-2 -> write fp32 to out_ext.
__global__ void k_agg(const float* __restrict__ bias, float* __restrict__ out_ext,
                      int act) {
    int t = threadIdx.x, lane = t & 31;
    int n = blockIdx.x * 8 + (t >> 5);
    float2 adp = *(const float2*)(g_ald + n * 2);
    int hs = lane >> 4;
    float adh = hs ? adp.y : adp.x;
    int beg = g_rowptr[n], end = g_rowptr[n + 1];

    float4 acc = make_float4(0.f, 0.f, 0.f, 0.f);
    float ssum = 0.f;

    // two-slot software pipeline: slots hold edges i (A) and i+1 (B)
    float aA = 0.f, aB = 0.f;
    uint2 uA = make_uint2(0u, 0u), uB = make_uint2(0u, 0u);
    int i = beg;
    if (i < end) {
        int s = g_esrc[i];
        aA = g_als[2 * s + hs];
        uA = ((const uint2*)(g_xwh + (size_t)s * DC))[lane];
    }
    if (i + 1 < end) {
        int s = g_esrc[i + 1];
        aB = g_als[2 * s + hs];
        uB = ((const uint2*)(g_xwh + (size_t)s * DC))[lane];
    }
    while (i < end) {
        {
            float a = aA; uint2 u = uA;
            if (i + 2 < end) {
                int s = g_esrc[i + 2];
                aA = g_als[2 * s + hs];
                uA = ((const uint2*)(g_xwh + (size_t)s * DC))[lane];
            }
            float w = __expf(lrelu(a + adh, NEG_GAT));
            ssum += w;
            float2 lo = __half22float2(*reinterpret_cast<__half2*>(&u.x));
            float2 hi = __half22float2(*reinterpret_cast<__half2*>(&u.y));
            acc.x = fmaf(lo.x, w, acc.x); acc.y = fmaf(lo.y, w, acc.y);
            acc.z = fmaf(hi.x, w, acc.z); acc.w = fmaf(hi.y, w, acc.w);
        }
        i++;
        if (i >= end) break;
        {
            float a = aB; uint2 u = uB;
            if (i + 2 < end) {
                int s = g_esrc[i + 2];
                aB = g_als[2 * s + hs];
                uB = ((const uint2*)(g_xwh + (size_t)s * DC))[lane];
            }
            float w = __expf(lrelu(a + adh, NEG_GAT));
            ssum += w;
            float2 lo = __half22float2(*reinterpret_cast<__half2*>(&u.x));
            float2 hi = __half22float2(*reinterpret_cast<__half2*>(&u.y));
            acc.x = fmaf(lo.x, w, acc.x); acc.y = fmaf(lo.y, w, acc.y);
            acc.z = fmaf(hi.x, w, acc.z); acc.w = fmaf(hi.y, w, acc.w);
        }
        i++;
    }
    float inv = 1.f / ssum;
    float4 b4 = __ldg((const float4*)bias + lane);
    float4 o4;
    o4.x = fmaf(acc.x, inv, b4.x); o4.y = fmaf(acc.y, inv, b4.y);
    o4.z = fmaf(acc.z, inv, b4.z); o4.w = fmaf(acc.w, inv, b4.w);
    if (act) {
        o4.x = lrelu(o4.x, NEG_ACT); o4.y = lrelu(o4.y, NEG_ACT);
        o4.z = lrelu(o4.z, NEG_ACT); o4.w = lrelu(o4.w, NEG_ACT);
        st_h4t(g_h1h, n, lane, o4.x, o4.y, o4.z, o4.w);
    } else {
        ((float4*)(out_ext + (size_t)n * DC))[lane] = o4;
    }
}

// ---------------- gate MLP: 8 nodes/warp + fused exp/gsum ----------------
__global__ void __launch_bounds__(256) k_gate(
        const float* __restrict__ hout, const float* __restrict__ gw1,
        const float* __restrict__ gb1, const float* __restrict__ gw2,
        const float* __restrict__ gb2, const int* __restrict__ batch) {
    __shared__ float Gs[DC * Dd];  // 32 KB
    int t = threadIdx.x, lane = t & 31, warp = t >> 5;
    for (int i = t; i < DC * Dd; i += 256) Gs[i] = gw1[i];
    __syncthreads();
    unsigned sb = (unsigned)__cvta_generic_to_shared(Gs);
    int n0 = blockIdx.x * 64 + warp * 8;
    float xv[8][4];
    unsigned long long ga[8];
    #pragma unroll
    for (int q = 0; q < 8; q++) {
        int nq = n0 + q; if (nq > Nn - 1) nq = Nn - 1;
        float4 r = ((const float4*)(hout + (size_t)nq * DC))[lane];
        xv[q][0] = r.x; xv[q][1] = r.y; xv[q][2] = r.z; xv[q][3] = r.w;
        ga[q] = 0;
    }
    #pragma unroll
    for (int k4 = 0; k4 < 32; k4++) {
        #pragma unroll
        for (int c = 0; c < 4; c++) {
            unsigned long long w;
            lds_u64(w, sb + (((4 * k4 + c) * 32 + lane) << 3));
            #pragma unroll
            for (int q = 0; q < 8; q++) {
                float b = __shfl_sync(~0u, xv[q][c], k4);
                pfma(ga[q], pk2(b), w);
            }
        }
    }
    float2 gb = __ldg((const float2*)gb1 + lane);
    float2 gw = __ldg((const float2*)gw2 + lane);
    float gbias = __ldg(gb2);
    #pragma unroll
    for (int q = 0; q < 8; q++) {
        float2 f = upk(ga[q]);
        float u0 = lrelu(f.x + gb.x, NEG_ACT);
        float u1 = lrelu(f.y + gb.y, NEG_ACT);
        float u = u0 * gw.x + u1 * gw.y;
        #pragma unroll
        for (int o = 16; o; o >>= 1) u += __shfl_xor_sync(~0u, u, o);
        int n = n0 + q;
        if (lane == 0 && n < Nn) {
            float ge = __expf(u + gbias);
            g_ge[n] = ge;
            atomicAdd(&g_gsum[batch[n]], ge);
        }
    }
}

// ---------------- segmented z aggregation (batch_idx is sorted) ----------------
#define ZCH 64
__global__ void k_zagg(const float* __restrict__ hout, float* __restrict__ zout,
                       const int* __restrict__ batch) {
    int t = threadIdx.x, lane = t & 31, warp = t >> 5;
    int w0 = blockIdx.x * 8 + warp;
    int n0 = w0 * ZCH;
    if (n0 >= Nn) return;
    int n1 = n0 + ZCH; if (n1 > Nn) n1 = Nn;
    float4 acc = make_float4(0.f, 0.f, 0.f, 0.f);
    int cg = batch[n0];
    for (int n = n0; n < n1; n++) {
        int g = batch[n];
        if (g != cg) {
            float* zb = zout + (size_t)cg * DC + lane * 4;
            atomicAdd(zb + 0, acc.x); atomicAdd(zb + 1, acc.y);
            atomicAdd(zb + 2, acc.z); atomicAdd(zb + 3, acc.w);
            acc = make_float4(0.f, 0.f, 0.f, 0.f);
            cg = g;
        }
        float w = g_ge[n] / g_gsum[g];
        float4 hv = ((const float4*)(hout + (size_t)n * DC))[lane];
        acc.x = fmaf(hv.x, w, acc.x); acc.y = fmaf(hv.y, w, acc.y);
        acc.z = fmaf(hv.z, w, acc.z); acc.w = fmaf(hv.w, w, acc.w);
    }
    float* zb = zout + (size_t)cg * DC + lane * 4;
    atomicAdd(zb + 0, acc.x); atomicAdd(zb + 1, acc.y);
    atomicAdd(zb + 2, acc.z); atomicAdd(zb + 3, acc.w);
}

// ---------------- launch (two-stream overlap: CSR build || embgemm1) ----------------
extern "C" void kernel_launch(void* const* d_in, const int* in_sizes, int n_in,
                              void* d_out, int out_size) {
    const int*   x     = (const int*)d_in[0];
    const int*   ei    = (const int*)d_in[1];
    const int*   batch = (const int*)d_in[2];
    const float* emb   = (const float*)d_in[3];
    const float* lng   = (const float*)d_in[4];
    const float* lnb   = (const float*)d_in[5];
    const float* W1    = (const float*)d_in[6];
    const float* as1   = (const float*)d_in[7];
    const float* ad1   = (const float*)d_in[8];
    const float* b1    = (const float*)d_in[9];
    const float* W2    = (const float*)d_in[10];
    const float* as2   = (const float*)d_in[11];
    const float* ad2   = (const float*)d_in[12];
    const float* b2    = (const float*)d_in[13];
    const float* gw1   = (const float*)d_in[14];
    const float* gb1   = (const float*)d_in[15];
    const float* gw2   = (const float*)d_in[16];
    const float* gb2   = (const float*)d_in[17];
    float* out  = (float*)d_out;
    float* zout = out + (size_t)Nn * DC;

    (void)in_sizes; (void)n_in; (void)out_size;

    static cudaStream_t s1 = nullptr;
    static cudaEvent_t evFork = nullptr, evJoin = nullptr;
    if (s1 == nullptr) {
        cudaStreamCreateWithFlags(&s1, cudaStreamNonBlocking);
        cudaEventCreateWithFlags(&evFork, cudaEventDisableTiming);
        cudaEventCreateWithFlags(&evJoin, cudaEventDisableTiming);
    }

    cudaStream_t s0 = 0;  // capture-origin (legacy) stream

    k_zero<<<512, 256, 0, s0>>>(zout);
    cudaEventRecord(evFork, s0);
    cudaStreamWaitEvent(s1, evFork, 0);

    // CSR build chain on side stream
    k_count<<<(Ee / 4 + 255) / 256, 256, 0, s1>>>(ei);
    k_scan_local<<<NB_SCAN, 256, 0, s1>>>();
    k_scan_mid<<<1, 32, 0, s1>>>();
    k_scan_add<<<(Nn + 255) / 256, 256, 0, s1>>>();
    k_scatter<<<(Ee / 4 + Nn + 255) / 256, 256, 0, s1>>>(ei);
    cudaEventRecord(evJoin, s1);

    // independent dense work on main stream (overlaps CSR build)
    k_embgemm1<<<(Nn + 31) / 32, 256, 0, s0>>>(x, emb, lng, lnb, W1, as1, ad1);

    cudaStreamWaitEvent(s0, evJoin, 0);

    k_agg<<<Nn / 8, 256, 0, s0>>>(b1, nullptr, 1);         // -> g_h1h (fp16)
    k_gemm2<<<(Nn + 63) / 64, 256, 0, s0>>>(W2, as2, ad2);
    k_agg<<<Nn / 8, 256, 0, s0>>>(b2, out, 0);             // -> d_out (h, fp32)
    k_gate<<<(Nn + 63) / 64, 256, 0, s0>>>(out, gw1, gb1, gw2, gb2, batch);
    int zwarps = (Nn + ZCH - 1) / ZCH;
    k_zagg<<<(zwarps + 7) / 8, 256, 0, s0>>>(out, zout, batch);
}